// round 6
// baseline (speedup 1.0000x reference)
#include <cuda_runtime.h>
#include <cstdint>

// Problem constants (from reference)
#define NROW0 50
#define NROW1 50
#define NROW2 50
#define NPAIR (NROW0 * NROW1)       // 2500 (d0,d1) combos
#define TROW  512                   // t row = 16 (k) x 32 (r2) floats
#define G1LEN 4096                  // core1 row: 32*4*32
#define G0LEN 128                   // core0 row: 1*4*32
#define G2LEN 256                   // core2 row: 32*8
#define EMBD  128

// Scratch (global, allocation-free)
__device__ __align__(16) float g_t_table[NPAIR * TROW];   // [p][k*32+r], 5.12 MB (L2)
__device__ __align__(16) float g_core2p[NROW2 * G2LEN];   // paired: [d2][u][r][2], 51.2 KB

// ---- f32x2 packed helpers -------------------------------------------------
__device__ __forceinline__ unsigned long long bcast2(float v) {
    unsigned long long r;
    asm("mov.b64 %0, {%1, %1};" : "=l"(r) : "f"(v));
    return r;
}
__device__ __forceinline__ void fma2(unsigned long long& d,
                                     unsigned long long a, unsigned long long b) {
    asm("fma.rn.f32x2 %0, %1, %2, %0;" : "+l"(d) : "l"(a), "l"(b));
}
__device__ __forceinline__ void add2(unsigned long long& d, unsigned long long o) {
    asm("add.rn.f32x2 %0, %0, %1;" : "+l"(d) : "l"(o));
}
__device__ __forceinline__ float lo_f(unsigned long long x) {
    return __uint_as_float((unsigned)x);
}
__device__ __forceinline__ float hi_f(unsigned long long x) {
    return __uint_as_float((unsigned)(x >> 32));
}

// ---------------------------------------------------------------------------
// Stage 1: t_table[p] = core0[d0] (4x32) @ core1[d1] (32x128)
// ---------------------------------------------------------------------------
__global__ void __launch_bounds__(128) tt_stage1(const float* __restrict__ core0,
                                                 const float* __restrict__ core1)
{
    __shared__ __align__(16) float s_g1[G1LEN];
    __shared__ __align__(16) float s_g0[G0LEN];
    const int p   = blockIdx.x;
    const int d0  = p / NROW1;
    const int d1  = p - d0 * NROW1;
    const int tid = threadIdx.x;

    const float4* __restrict__ g1v = (const float4*)(core1 + (size_t)d1 * G1LEN);
    float4* s1v = (float4*)s_g1;
    #pragma unroll
    for (int t = 0; t < G1LEN / 4 / 128; ++t)
        s1v[t * 128 + tid] = __ldg(g1v + t * 128 + tid);
    if (tid < G0LEN / 4)
        ((float4*)s_g0)[tid] = __ldg((const float4*)(core0 + d0 * G0LEN) + tid);
    __syncthreads();

    float a0 = 0.f, a1 = 0.f, a2 = 0.f, a3 = 0.f;
    #pragma unroll
    for (int r = 0; r < 32; ++r) {
        const float g1v_ = s_g1[r * 128 + tid];
        a0 = fmaf(s_g0[r],      g1v_, a0);
        a1 = fmaf(s_g0[32 + r], g1v_, a1);
        a2 = fmaf(s_g0[64 + r], g1v_, a2);
        a3 = fmaf(s_g0[96 + r], g1v_, a3);
    }
    float* o = g_t_table + (size_t)p * TROW;
    o[tid]       = a0;
    o[tid + 128] = a1;
    o[tid + 256] = a2;
    o[tid + 384] = a3;
}

// ---------------------------------------------------------------------------
// Pair-transpose core2: [d2][r*8+z] -> g_core2p float2 pairs
//   float2 #(d2*128 + u*32 + r) = { core2[d2][r*8+2u], core2[d2][r*8+2u+1] }
// ---------------------------------------------------------------------------
__global__ void __launch_bounds__(256) core2_pair(const float* __restrict__ core2)
{
    const int v = blockIdx.x * 256 + threadIdx.x;   // output float position
    if (v >= NROW2 * G2LEN) return;
    const int d2   = v >> 8;
    const int rem  = v & 255;        // u*64 + r*2 + h
    const int u    = rem >> 6;
    const int r    = (rem & 63) >> 1;
    const int h    = rem & 1;
    g_core2p[v] = core2[(d2 << 8) + r * 8 + 2 * u + h];
}

// ---------------------------------------------------------------------------
// Stage 2: one bag per block; each index handled by one warp (4-way split).
// Lane (q=lane>>3, c8=lane&7):
//   t:  4 float4  t[p][(q*4+m)*32 + c8*4 ..]          (full 2KB row per warp)
//   c:  16 uint64 f32x2 pairs cp[d2][u][c8*4..c8*4+3] (z=2u,2u+1 packed)
//   acc[m][u] (f32x2) += bcast2(t[m].r) * cp[u][r]    -> 64 packed FMA/index
// Bag end: packed xor-shfl+add2 over 8 c-lanes; lane keeps z==c8
// (u=c8>>1, half=c8&1); cross-warp combine via smem[4][128].
// ---------------------------------------------------------------------------
__global__ void __launch_bounds__(128, 4) bag_kernel(
    const int*   __restrict__ indices,
    const int*   __restrict__ offsets,
    const int*   __restrict__ cached_indices,
    const int*   __restrict__ cached_offsets,
    const float* __restrict__ cache_table,
    float*       __restrict__ out,
    int num_bags)
{
    __shared__ float s_part[4][EMBD];
    const int tid  = threadIdx.x;
    const int w    = tid >> 5;
    const int lane = tid & 31;
    const int q    = lane >> 3;
    const int c8   = lane & 7;

    for (int b = blockIdx.x; b < num_bags; b += gridDim.x) {
        const int i0 = __ldg(offsets + b);
        const int i1 = __ldg(offsets + b + 1);

        unsigned long long acc[4][4];
        #pragma unroll
        for (int m = 0; m < 4; ++m)
            #pragma unroll
            for (int u = 0; u < 4; ++u) acc[m][u] = 0ull;

        for (int i = i0 + w; i < i1; i += 4) {
            const int idx = __ldg(indices + i);
            const int pq  = idx / 50;
            const int d2  = idx - pq * 50;

            const float4* __restrict__ tr =
                (const float4*)g_t_table + pq * 128 + q * 32 + c8;
            float4 t0 = __ldg(tr);
            float4 t1 = __ldg(tr + 8);
            float4 t2 = __ldg(tr + 16);
            float4 t3 = __ldg(tr + 24);

            const ulonglong2* __restrict__ cp =
                (const ulonglong2*)g_core2p + d2 * 64 + c8 * 2;
            unsigned long long cu[4][4];
            #pragma unroll
            for (int u = 0; u < 4; ++u) {
                ulonglong2 ca = __ldg(cp + u * 16);
                ulonglong2 cb = __ldg(cp + u * 16 + 1);
                cu[u][0] = ca.x; cu[u][1] = ca.y;
                cu[u][2] = cb.x; cu[u][3] = cb.y;
            }

            unsigned long long tb;
            #define DO_R(TV, M, R)                                   \
                tb = bcast2(TV);                                     \
                fma2(acc[M][0], tb, cu[0][R]);                       \
                fma2(acc[M][1], tb, cu[1][R]);                       \
                fma2(acc[M][2], tb, cu[2][R]);                       \
                fma2(acc[M][3], tb, cu[3][R]);
            DO_R(t0.x, 0, 0) DO_R(t0.y, 0, 1) DO_R(t0.z, 0, 2) DO_R(t0.w, 0, 3)
            DO_R(t1.x, 1, 0) DO_R(t1.y, 1, 1) DO_R(t1.z, 1, 2) DO_R(t1.w, 1, 3)
            DO_R(t2.x, 2, 0) DO_R(t2.y, 2, 1) DO_R(t2.z, 2, 2) DO_R(t2.w, 2, 3)
            DO_R(t3.x, 3, 0) DO_R(t3.y, 3, 1) DO_R(t3.z, 3, 2) DO_R(t3.w, 3, 3)
            #undef DO_R
        }

        // Packed reduce across the 8 c-lanes of each q-group.
        #pragma unroll
        for (int off = 1; off < 8; off <<= 1)
            #pragma unroll
            for (int m = 0; m < 4; ++m)
                #pragma unroll
                for (int u = 0; u < 4; ++u)
                    add2(acc[m][u],
                         __shfl_xor_sync(0xffffffffu, acc[m][u], off));

        // Lane keeps z == c8: u = c8>>1, half = c8&1.
        float v0, v1, v2, v3;
        #define EXTR(U, HIF)                                         \
            v0 = HIF(acc[0][U]); v1 = HIF(acc[1][U]);                \
            v2 = HIF(acc[2][U]); v3 = HIF(acc[3][U]);
        switch (c8) {
            case 0: EXTR(0, lo_f) break;
            case 1: EXTR(0, hi_f) break;
            case 2: EXTR(1, lo_f) break;
            case 3: EXTR(1, hi_f) break;
            case 4: EXTR(2, lo_f) break;
            case 5: EXTR(2, hi_f) break;
            case 6: EXTR(3, lo_f) break;
            default: EXTR(3, hi_f) break;
        }
        #undef EXTR

        const int e0 = q * 32 + c8;      // element = q*32 + m*8 + c8
        s_part[w][e0]      = v0;
        s_part[w][e0 + 8]  = v1;
        s_part[w][e0 + 16] = v2;
        s_part[w][e0 + 24] = v3;
        __syncthreads();

        const float tt = (s_part[0][tid] + s_part[1][tid])
                       + (s_part[2][tid] + s_part[3][tid]);

        // ---- cached-table bag (coalesced row gather, 4x unrolled) ----
        const int j0 = __ldg(cached_offsets + b);
        const int j1 = __ldg(cached_offsets + b + 1);
        float cacc = 0.f;
        int j = j0;
        for (; j + 4 <= j1; j += 4) {
            const int a0i = __ldg(cached_indices + j);
            const int a1i = __ldg(cached_indices + j + 1);
            const int a2i = __ldg(cached_indices + j + 2);
            const int a3i = __ldg(cached_indices + j + 3);
            const float f0 = __ldg(cache_table + (size_t)a0i * EMBD + tid);
            const float f1 = __ldg(cache_table + (size_t)a1i * EMBD + tid);
            const float f2 = __ldg(cache_table + (size_t)a2i * EMBD + tid);
            const float f3 = __ldg(cache_table + (size_t)a3i * EMBD + tid);
            cacc += (f0 + f1) + (f2 + f3);
        }
        for (; j < j1; ++j)
            cacc += __ldg(cache_table + (size_t)__ldg(cached_indices + j) * EMBD + tid);

        out[(size_t)b * EMBD + tid] = tt + cacc;
        __syncthreads();   // s_part reuse safety (grid-stride)
    }
}

// ---------------------------------------------------------------------------
extern "C" void kernel_launch(void* const* d_in, const int* in_sizes, int n_in,
                              void* d_out, int out_size)
{
    const int*   indices        = (const int*)d_in[0];
    const int*   offsets        = (const int*)d_in[1];
    const int*   cached_indices = (const int*)d_in[2];
    const int*   cached_offsets = (const int*)d_in[3];
    const float* core0          = (const float*)d_in[4];
    const float* core1          = (const float*)d_in[5];
    const float* core2          = (const float*)d_in[6];
    const float* cache_table    = (const float*)d_in[7];
    float* out = (float*)d_out;

    const int num_bags = out_size / EMBD;   // 4096

    tt_stage1<<<NPAIR, 128>>>(core0, core1);
    core2_pair<<<(NROW2 * G2LEN + 255) / 256, 256>>>(core2);

    bag_kernel<<<num_bags, 128>>>(indices, offsets, cached_indices, cached_offsets,
                                  cache_table, out, num_bags);
}